// round 3
// baseline (speedup 1.0000x reference)
#include <cuda_runtime.h>

#define NSHAPES 32
#define TPB 256
#define PPT 4           // points per thread (2 float4 loads, 1 float4 store)

typedef unsigned long long u64;

__device__ __forceinline__ u64 ffma2(u64 a, u64 b, u64 c) {
    u64 d;
    asm("fma.rn.f32x2 %0, %1, %2, %3;" : "=l"(d) : "l"(a), "l"(b), "l"(c));
    return d;
}
__device__ __forceinline__ u64 pack2(float lo, float hi) {
    u64 d;
    asm("mov.b64 %0, {%1, %2};" : "=l"(d) : "f"(lo), "f"(hi));
    return d;
}
__device__ __forceinline__ void unpack2(u64 v, float& lo, float& hi) {
    asm("mov.b64 {%0, %1}, %2;" : "=f"(lo), "=f"(hi) : "l"(v));
}
__device__ __forceinline__ float sqrt_approx(float x) {
    float r;
    asm("sqrt.approx.f32 %0, %1;" : "=f"(r) : "f"(x));
    return r;
}

__global__ __launch_bounds__(TPB)
void multi_rect_sdf_kernel(const float* __restrict__ query,
                           const float* __restrict__ trans,
                           const float* __restrict__ rads,
                           const float* __restrict__ angles,
                           float* __restrict__ out,
                           int npts)
{
    // Per-shape constants, 4 packed u64 per shape (32B, 16B-aligned):
    //   [0] (c, s)   [1] (-s, c)   [2] (-tx, -ty)   [3] (-rx, -ry)
    __shared__ __align__(16) u64 shc[NSHAPES * 4];

    const int t = threadIdx.x;
    if (t < NSHAPES) {
        float ang = angles[t];
        float c = cosf(ang), s = sinf(ang);
        float tx = trans[2 * t], ty = trans[2 * t + 1];
        float rx = rads[2 * t],  ry = rads[2 * t + 1];
        shc[4 * t + 0] = pack2(c, s);
        shc[4 * t + 1] = pack2(-s, c);
        shc[4 * t + 2] = pack2(-tx, -ty);
        shc[4 * t + 3] = pack2(-rx, -ry);
    }
    __syncthreads();

    // Thread t handles PPT consecutive points -> float4-coalesced I/O.
    const int p0 = blockIdx.x * (TPB * PPT) + t * PPT;
    const bool full = (p0 + PPT) <= npts;    // true for every block at N=2M

    // Per-point duplicated packing: QXX[i]=(x,x), QYY[i]=(y,y). Built once,
    // so the 32-shape loop has ZERO cross-lane repacking.
    u64 QXX[PPT], QYY[PPT];
    if (full) {
        float4 qa = *reinterpret_cast<const float4*>(query + (size_t)p0 * 2);
        float4 qb = *reinterpret_cast<const float4*>(query + (size_t)p0 * 2 + 4);
        QXX[0] = pack2(qa.x, qa.x);  QYY[0] = pack2(qa.y, qa.y);
        QXX[1] = pack2(qa.z, qa.z);  QYY[1] = pack2(qa.w, qa.w);
        QXX[2] = pack2(qb.x, qb.x);  QYY[2] = pack2(qb.y, qb.y);
        QXX[3] = pack2(qb.z, qb.z);  QYY[3] = pack2(qb.w, qb.w);
    } else {
#pragma unroll
        for (int i = 0; i < PPT; i++) {
            int p = p0 + i;
            float x = 0.f, y = 0.f;
            if (p < npts) { x = query[(size_t)p * 2]; y = query[(size_t)p * 2 + 1]; }
            QXX[i] = pack2(x, x);
            QYY[i] = pack2(y, y);
        }
    }

    float mS[PPT], mI[PPT];
#pragma unroll
    for (int i = 0; i < PPT; i++) { mS[i] = 3.0e38f; mI[i] = 3.0e38f; }

#pragma unroll 4
    for (int j = 0; j < NSHAPES; j++) {
        const u64 CS  = shc[4 * j + 0];   // (c, s)
        const u64 NSC = shc[4 * j + 1];   // (-s, c)
        const u64 NT  = shc[4 * j + 2];   // (-tx, -ty)
        float nrx, nry;
        unpack2(shc[4 * j + 3], nrx, nry);  // (-rx, -ry)

#pragma unroll
        for (int i = 0; i < PPT; i++) {
            // (rx', ry') for one point in a single packed pair:
            //   rx' =  c*x - s*y - tx,  ry' = s*x + c*y - ty
            u64 A = ffma2(CS, QXX[i], ffma2(NSC, QYY[i], NT));
            float ax, ay;
            unpack2(A, ax, ay);              // register-pair halves (free)

            float dx = fabsf(ax) + nrx;      // FADD |.|-r      (fma pipe)
            float dy = fabsf(ay) + nry;
            float mx = fmaxf(dx, 0.f);       // FMNMX           (alu pipe)
            float my = fmaxf(dy, 0.f);
            float sq = fmaf(my, my, mx * mx);
            mS[i] = fminf(mS[i], sq);
            mI[i] = fminf(mI[i], fmaxf(dx, dy));
        }
    }

    if (full) {
        float4 r;
        r.x = (mI[0] < 0.f) ? mI[0] : sqrt_approx(mS[0]);
        r.y = (mI[1] < 0.f) ? mI[1] : sqrt_approx(mS[1]);
        r.z = (mI[2] < 0.f) ? mI[2] : sqrt_approx(mS[2]);
        r.w = (mI[3] < 0.f) ? mI[3] : sqrt_approx(mS[3]);
        *reinterpret_cast<float4*>(out + p0) = r;
    } else {
#pragma unroll
        for (int i = 0; i < PPT; i++) {
            int p = p0 + i;
            if (p < npts)
                out[p] = (mI[i] < 0.f) ? mI[i] : sqrt_approx(mS[i]);
        }
    }
}

extern "C" void kernel_launch(void* const* d_in, const int* in_sizes, int n_in,
                              void* d_out, int out_size)
{
    const float* query  = (const float*)d_in[0];   // (N, 2)
    const float* trans  = (const float*)d_in[1];   // (32, 2)
    const float* rads   = (const float*)d_in[2];   // (32, 2)
    const float* angles = (const float*)d_in[3];   // (32,)
    float* out = (float*)d_out;

    int npts = in_sizes[0] / 2;
    int pts_per_block = TPB * PPT;
    int nblocks = (npts + pts_per_block - 1) / pts_per_block;

    multi_rect_sdf_kernel<<<nblocks, TPB>>>(query, trans, rads, angles, out, npts);
}

// round 4
// speedup vs baseline: 1.0009x; 1.0009x over previous
#include <cuda_runtime.h>

#define NSHAPES 32
#define TPB 256
#define PPT 8           // points per thread (4 float4 loads, 2 float4 stores)

typedef unsigned long long u64;

__device__ __forceinline__ u64 ffma2(u64 a, u64 b, u64 c) {
    u64 d;
    asm("fma.rn.f32x2 %0, %1, %2, %3;" : "=l"(d) : "l"(a), "l"(b), "l"(c));
    return d;
}
__device__ __forceinline__ u64 pack2(float lo, float hi) {
    u64 d;
    asm("mov.b64 %0, {%1, %2};" : "=l"(d) : "f"(lo), "f"(hi));
    return d;
}
__device__ __forceinline__ void unpack2(u64 v, float& lo, float& hi) {
    asm("mov.b64 {%0, %1}, %2;" : "=f"(lo), "=f"(hi) : "l"(v));
}
__device__ __forceinline__ float sqrt_approx(float x) {
    float r;
    asm("sqrt.approx.f32 %0, %1;" : "=f"(r) : "f"(x));
    return r;
}

__global__ __launch_bounds__(TPB)
void multi_rect_sdf_kernel(const float* __restrict__ query,
                           const float* __restrict__ trans,
                           const float* __restrict__ rads,
                           const float* __restrict__ angles,
                           float* __restrict__ out,
                           int npts)
{
    // Per-shape constants, 4 packed u64 per shape (32B, 16B-aligned):
    //   [0] (c, s)   [1] (-s, c)   [2] (-tx, -ty)   [3] (-rx, -ry)
    __shared__ __align__(16) u64 shc[NSHAPES * 4];

    const int t = threadIdx.x;
    if (t < NSHAPES) {
        float ang = angles[t];
        float c = cosf(ang), s = sinf(ang);
        float tx = trans[2 * t], ty = trans[2 * t + 1];
        float rx = rads[2 * t],  ry = rads[2 * t + 1];
        shc[4 * t + 0] = pack2(c, s);
        shc[4 * t + 1] = pack2(-s, c);
        shc[4 * t + 2] = pack2(-tx, -ty);
        shc[4 * t + 3] = pack2(-rx, -ry);
    }
    __syncthreads();

    // Thread t handles PPT consecutive points -> float4-coalesced I/O.
    const int p0 = blockIdx.x * (TPB * PPT) + t * PPT;
    const bool full = (p0 + PPT) <= npts;    // true for every block at N=2M

    // Per-point duplicated packing: QXX[i]=(x,x), QYY[i]=(y,y). Built once,
    // so the 32-shape loop has ZERO cross-lane repacking.
    u64 QXX[PPT], QYY[PPT];
    if (full) {
#pragma unroll
        for (int h = 0; h < PPT / 2; h++) {
            float4 q = *reinterpret_cast<const float4*>(query + (size_t)p0 * 2 + h * 4);
            QXX[2 * h]     = pack2(q.x, q.x);  QYY[2 * h]     = pack2(q.y, q.y);
            QXX[2 * h + 1] = pack2(q.z, q.z);  QYY[2 * h + 1] = pack2(q.w, q.w);
        }
    } else {
#pragma unroll
        for (int i = 0; i < PPT; i++) {
            int p = p0 + i;
            float x = 0.f, y = 0.f;
            if (p < npts) { x = query[(size_t)p * 2]; y = query[(size_t)p * 2 + 1]; }
            QXX[i] = pack2(x, x);
            QYY[i] = pack2(y, y);
        }
    }

    // Single accumulator: E = min over shapes of (sq + min(max(dx,dy),0)).
    // For an outside shape the 2nd term is 0 (e = sq >= 0); for an inside
    // shape sq = 0 (e = inside <= 0). Negatives beat positives in the min,
    // so E<0 => answer E, else answer sqrt(E). Exact vs reference.
    float E[PPT];
#pragma unroll
    for (int i = 0; i < PPT; i++) E[i] = 3.0e38f;

#pragma unroll 4
    for (int j = 0; j < NSHAPES; j++) {
        const u64 CS  = shc[4 * j + 0];   // (c, s)
        const u64 NSC = shc[4 * j + 1];   // (-s, c)
        const u64 NT  = shc[4 * j + 2];   // (-tx, -ty)
        float nrx, nry;
        unpack2(shc[4 * j + 3], nrx, nry);  // (-rx, -ry)

#pragma unroll
        for (int i = 0; i < PPT; i++) {
            // (rx', ry') for one point in a single packed pair:
            //   rx' =  c*x - s*y - tx,  ry' = s*x + c*y - ty
            u64 A = ffma2(CS, QXX[i], ffma2(NSC, QYY[i], NT));
            float ax, ay;
            unpack2(A, ax, ay);

            float dx = fabsf(ax) + nrx;        // FADD |.|+(-r)  (fma pipe)
            float dy = fabsf(ay) + nry;
            float mx = fmaxf(dx, 0.f);         // FMNMX          (alu pipe)
            float my = fmaxf(dy, 0.f);
            float ic = fminf(fmaxf(dx, dy), 0.f);
            float e  = fmaf(mx, mx, fmaf(my, my, ic));
            E[i] = fminf(E[i], e);
        }
    }

    if (full) {
#pragma unroll
        for (int h = 0; h < PPT / 4; h++) {
            float4 r;
            float* e4 = &E[4 * h];
            r.x = (e4[0] < 0.f) ? e4[0] : sqrt_approx(e4[0]);
            r.y = (e4[1] < 0.f) ? e4[1] : sqrt_approx(e4[1]);
            r.z = (e4[2] < 0.f) ? e4[2] : sqrt_approx(e4[2]);
            r.w = (e4[3] < 0.f) ? e4[3] : sqrt_approx(e4[3]);
            *reinterpret_cast<float4*>(out + p0 + 4 * h) = r;
        }
    } else {
#pragma unroll
        for (int i = 0; i < PPT; i++) {
            int p = p0 + i;
            if (p < npts)
                out[p] = (E[i] < 0.f) ? E[i] : sqrt_approx(E[i]);
        }
    }
}

extern "C" void kernel_launch(void* const* d_in, const int* in_sizes, int n_in,
                              void* d_out, int out_size)
{
    const float* query  = (const float*)d_in[0];   // (N, 2)
    const float* trans  = (const float*)d_in[1];   // (32, 2)
    const float* rads   = (const float*)d_in[2];   // (32, 2)
    const float* angles = (const float*)d_in[3];   // (32,)
    float* out = (float*)d_out;

    int npts = in_sizes[0] / 2;
    int pts_per_block = TPB * PPT;
    int nblocks = (npts + pts_per_block - 1) / pts_per_block;

    multi_rect_sdf_kernel<<<nblocks, TPB>>>(query, trans, rads, angles, out, npts);
}